// round 1
// baseline (speedup 1.0000x reference)
#include <cuda_runtime.h>
#include <math.h>

// Problem constants (fixed by the dataset)
#define NMAX 100000
#define EMAX 1600000

// ---------------- scratch (device globals; no allocations allowed) ----------
__device__ float g_h1[NMAX * 128];   // layer1 pre-attention features [N,8,16]
__device__ float g_as1[NMAX * 8];    // a_s per node, layer1
__device__ float g_ad1[NMAX * 8];    // a_d per node, layer1
__device__ float g_x2[NMAX * 128];   // elu(out1 + b1)
__device__ float g_h2[NMAX * 64];    // layer2 features
__device__ float g_as2[NMAX];
__device__ float g_ad2[NMAX];
__device__ int   g_rowptr[NMAX + 1];
__device__ int   g_cnt[NMAX];
__device__ int   g_fill[NMAX];
__device__ int   g_srcs[EMAX];       // CSR-sorted src per (dst-grouped) edge

__device__ __forceinline__ float lrelu(float x) { return x > 0.f ? x : 0.2f * x; }
__device__ __forceinline__ float elu1(float x)  { return x > 0.f ? x : (__expf(x) - 1.f); }

// ---------------- CSR build ---------------------------------------------------
__global__ void zero_cnt_kernel(int n) {
    int i = blockIdx.x * blockDim.x + threadIdx.x;
    if (i < n) g_cnt[i] = 0;
}

__global__ void hist_kernel(const int* __restrict__ ei, int e) {
    int i = blockIdx.x * blockDim.x + threadIdx.x;
    if (i < e) atomicAdd(&g_cnt[ei[e + i]], 1);   // dst row
}

// single-block exclusive scan of g_cnt -> g_rowptr (warp-shuffle based)
__global__ void scan_kernel(int n) {
    __shared__ int wsum[32];
    __shared__ int carry;
    int t = threadIdx.x, lane = t & 31, wid = t >> 5;
    if (t == 0) { carry = 0; g_rowptr[0] = 0; }
    __syncthreads();
    for (int base = 0; base < n; base += 1024) {
        int i = base + t;
        int v = (i < n) ? g_cnt[i] : 0;
        int x = v;
        #pragma unroll
        for (int off = 1; off < 32; off <<= 1) {
            int u = __shfl_up_sync(0xffffffffu, x, off);
            if (lane >= off) x += u;
        }
        if (lane == 31) wsum[wid] = x;
        __syncthreads();
        if (wid == 0) {
            int s = wsum[lane];
            #pragma unroll
            for (int off = 1; off < 32; off <<= 1) {
                int u = __shfl_up_sync(0xffffffffu, s, off);
                if (lane >= off) s += u;
            }
            wsum[lane] = s;
        }
        __syncthreads();
        int pre = (wid > 0) ? wsum[wid - 1] : 0;
        int incl = carry + pre + x;
        if (i < n) g_rowptr[i + 1] = incl;
        int total = wsum[31];
        __syncthreads();
        if (t == 0) carry += total;
        __syncthreads();
    }
}

__global__ void copy_fill_kernel(int n) {
    int i = blockIdx.x * blockDim.x + threadIdx.x;
    if (i < n) g_fill[i] = g_rowptr[i];
}

__global__ void scatter_kernel(const int* __restrict__ ei, int e) {
    int i = blockIdx.x * blockDim.x + threadIdx.x;
    if (i < e) {
        int s = ei[i];
        int d = ei[e + i];
        int pos = atomicAdd(&g_fill[d], 1);
        g_srcs[pos] = s;
    }
}

// ---------------- GEMM1: h1 = x @ W1  (MxK @ KxN, K=256, N=128) ---------------
__global__ void gemm1_kernel(const float* __restrict__ A, const float* __restrict__ B, int M) {
    const int K = 256, NC = 128;
    __shared__ float As[32][65];
    __shared__ float Bs[32][128];
    int tid = threadIdx.x;
    int blockRow = blockIdx.x * 64;
    int aRow = tid >> 3;          // 0..31
    int aCol = (tid & 7) << 2;    // 0..28
    int bRow = tid >> 5;          // 0..7
    int bCol = (tid & 31) << 2;   // 0..124
    int tRow = (tid >> 4) << 2;   // 0..60
    int tCol = (tid & 15) << 3;   // 0..120
    float acc[4][8];
    #pragma unroll
    for (int i = 0; i < 4; i++)
        #pragma unroll
        for (int j = 0; j < 8; j++) acc[i][j] = 0.f;

    for (int k0 = 0; k0 < K; k0 += 32) {
        #pragma unroll
        for (int r = 0; r < 2; r++) {
            int row = blockRow + aRow + r * 32;
            float4 v = (row < M) ? *(const float4*)(A + (size_t)row * K + k0 + aCol)
                                 : make_float4(0.f, 0.f, 0.f, 0.f);
            As[aCol + 0][aRow + r * 32] = v.x;
            As[aCol + 1][aRow + r * 32] = v.y;
            As[aCol + 2][aRow + r * 32] = v.z;
            As[aCol + 3][aRow + r * 32] = v.w;
        }
        #pragma unroll
        for (int r = 0; r < 4; r++) {
            int row = bRow + r * 8;
            *(float4*)&Bs[row][bCol] = *(const float4*)(B + (size_t)(k0 + row) * NC + bCol);
        }
        __syncthreads();
        #pragma unroll
        for (int k = 0; k < 32; k++) {
            float a0 = As[k][tRow], a1 = As[k][tRow + 1], a2 = As[k][tRow + 2], a3 = As[k][tRow + 3];
            float4 bv0 = *(float4*)&Bs[k][tCol];
            float4 bv1 = *(float4*)&Bs[k][tCol + 4];
            float bj[8] = {bv0.x, bv0.y, bv0.z, bv0.w, bv1.x, bv1.y, bv1.z, bv1.w};
            float ai[4] = {a0, a1, a2, a3};
            #pragma unroll
            for (int i = 0; i < 4; i++)
                #pragma unroll
                for (int j = 0; j < 8; j++) acc[i][j] += ai[i] * bj[j];
        }
        __syncthreads();
    }
    #pragma unroll
    for (int i = 0; i < 4; i++) {
        int row = blockRow + tRow + i;
        if (row < M) {
            *(float4*)&g_h1[(size_t)row * 128 + tCol]     = make_float4(acc[i][0], acc[i][1], acc[i][2], acc[i][3]);
            *(float4*)&g_h1[(size_t)row * 128 + tCol + 4] = make_float4(acc[i][4], acc[i][5], acc[i][6], acc[i][7]);
        }
    }
}

// ---------------- attention coefficients, layer 1 ----------------------------
__global__ void att1_kernel(const float* __restrict__ att_s, const float* __restrict__ att_d, int n) {
    int idx = blockIdx.x * blockDim.x + threadIdx.x;
    if (idx >= n * 8) return;
    int node = idx >> 3, h = idx & 7;
    const float* hp = &g_h1[(size_t)node * 128 + h * 16];
    float s = 0.f, d = 0.f;
    #pragma unroll
    for (int c = 0; c < 16; c++) {
        float v = hp[c];
        s += v * __ldg(&att_s[h * 16 + c]);
        d += v * __ldg(&att_d[h * 16 + c]);
    }
    g_as1[idx] = s;
    g_ad1[idx] = d;
}

// ---------------- layer-1 gather/softmax/aggregate (+bias+ELU) ---------------
// one warp per dst node; lane owns output channels [4*lid, 4*lid+4); head = lid>>2
__global__ void gat1_kernel(const float* __restrict__ b1, int n) {
    int warp = (blockIdx.x * blockDim.x + threadIdx.x) >> 5;
    int lid = threadIdx.x & 31;
    if (warp >= n) return;
    int beg = g_rowptr[warp], end = g_rowptr[warp + 1];

    float adh[8];
    {
        float4 a = *(const float4*)&g_ad1[warp * 8];
        float4 b = *(const float4*)&g_ad1[warp * 8 + 4];
        adh[0] = a.x; adh[1] = a.y; adh[2] = a.z; adh[3] = a.w;
        adh[4] = b.x; adh[5] = b.y; adh[6] = b.z; adh[7] = b.w;
    }
    float mx[8];
    #pragma unroll
    for (int k = 0; k < 8; k++) mx[k] = -1e30f;

    // pass 1: per-head max of leaky_relu(a_s[src]+a_d[dst]) (lane-strided edges)
    for (int e = beg + lid; e < end; e += 32) {
        int s = g_srcs[e];
        float4 a = *(const float4*)&g_as1[s * 8];
        float4 b = *(const float4*)&g_as1[s * 8 + 4];
        mx[0] = fmaxf(mx[0], lrelu(a.x + adh[0]));
        mx[1] = fmaxf(mx[1], lrelu(a.y + adh[1]));
        mx[2] = fmaxf(mx[2], lrelu(a.z + adh[2]));
        mx[3] = fmaxf(mx[3], lrelu(a.w + adh[3]));
        mx[4] = fmaxf(mx[4], lrelu(b.x + adh[4]));
        mx[5] = fmaxf(mx[5], lrelu(b.y + adh[5]));
        mx[6] = fmaxf(mx[6], lrelu(b.z + adh[6]));
        mx[7] = fmaxf(mx[7], lrelu(b.w + adh[7]));
    }
    #pragma unroll
    for (int k = 0; k < 8; k++) {
        #pragma unroll
        for (int off = 16; off; off >>= 1)
            mx[k] = fmaxf(mx[k], __shfl_xor_sync(0xffffffffu, mx[k], off));
    }

    int h = lid >> 2;
    float acc0 = 0.f, acc1 = 0.f, acc2 = 0.f, acc3 = 0.f;
    float denom = 0.f;

    // pass 2: weighted accumulate (warp processes one edge at a time)
    for (int e = beg; e < end; e++) {
        int s = g_srcs[e];
        float w = 0.f;
        if (lid < 8) {
            float a = __ldg(&g_as1[s * 8 + lid]);
            w = __expf(lrelu(a + adh[lid]) - mx[lid]);
            denom += w;
        }
        float wh = __shfl_sync(0xffffffffu, w, h);
        float4 v = *(const float4*)&g_h1[(size_t)s * 128 + lid * 4];
        acc0 += wh * v.x;
        acc1 += wh * v.y;
        acc2 += wh * v.z;
        acc3 += wh * v.w;
    }
    float dh = __shfl_sync(0xffffffffu, denom, h);
    float inv = 1.f / (dh + 1e-16f);
    float4 bb = *(const float4*)&b1[lid * 4];
    float4 o;
    o.x = elu1(acc0 * inv + bb.x);
    o.y = elu1(acc1 * inv + bb.y);
    o.z = elu1(acc2 * inv + bb.z);
    o.w = elu1(acc3 * inv + bb.w);
    *(float4*)&g_x2[(size_t)warp * 128 + lid * 4] = o;
}

// ---------------- GEMM2: h2 = x2 @ W2  (K=128, N=64) --------------------------
__global__ void gemm2_kernel(const float* __restrict__ B, int M) {
    const int K = 128, NC = 64;
    __shared__ float As[32][65];
    __shared__ float Bs[32][64];
    int tid = threadIdx.x;
    int blockRow = blockIdx.x * 64;
    int aRow = tid >> 3;          // 0..31
    int aCol = (tid & 7) << 2;
    int bRow = tid >> 4;          // 0..15
    int bCol = (tid & 15) << 2;   // 0..60
    int tRow = (tid >> 4) << 2;
    int tCol = (tid & 15) << 2;
    const float* A = g_x2;
    float acc[4][4];
    #pragma unroll
    for (int i = 0; i < 4; i++)
        #pragma unroll
        for (int j = 0; j < 4; j++) acc[i][j] = 0.f;

    for (int k0 = 0; k0 < K; k0 += 32) {
        #pragma unroll
        for (int r = 0; r < 2; r++) {
            int row = blockRow + aRow + r * 32;
            float4 v = (row < M) ? *(const float4*)(A + (size_t)row * K + k0 + aCol)
                                 : make_float4(0.f, 0.f, 0.f, 0.f);
            As[aCol + 0][aRow + r * 32] = v.x;
            As[aCol + 1][aRow + r * 32] = v.y;
            As[aCol + 2][aRow + r * 32] = v.z;
            As[aCol + 3][aRow + r * 32] = v.w;
        }
        #pragma unroll
        for (int r = 0; r < 2; r++) {
            int row = bRow + r * 16;
            *(float4*)&Bs[row][bCol] = *(const float4*)(B + (size_t)(k0 + row) * NC + bCol);
        }
        __syncthreads();
        #pragma unroll
        for (int k = 0; k < 32; k++) {
            float a0 = As[k][tRow], a1 = As[k][tRow + 1], a2 = As[k][tRow + 2], a3 = As[k][tRow + 3];
            float4 bv = *(float4*)&Bs[k][tCol];
            float bj[4] = {bv.x, bv.y, bv.z, bv.w};
            float ai[4] = {a0, a1, a2, a3};
            #pragma unroll
            for (int i = 0; i < 4; i++)
                #pragma unroll
                for (int j = 0; j < 4; j++) acc[i][j] += ai[i] * bj[j];
        }
        __syncthreads();
    }
    #pragma unroll
    for (int i = 0; i < 4; i++) {
        int row = blockRow + tRow + i;
        if (row < M)
            *(float4*)&g_h2[(size_t)row * 64 + tCol] = make_float4(acc[i][0], acc[i][1], acc[i][2], acc[i][3]);
    }
}

// ---------------- attention coefficients, layer 2 (warp per node) -------------
__global__ void att2_kernel(const float* __restrict__ att_s, const float* __restrict__ att_d, int n) {
    int warp = (blockIdx.x * blockDim.x + threadIdx.x) >> 5;
    int lid = threadIdx.x & 31;
    if (warp >= n) return;
    float2 v = *(const float2*)&g_h2[(size_t)warp * 64 + lid * 2];
    float2 as = __ldg((const float2*)(att_s + lid * 2));
    float2 ad = __ldg((const float2*)(att_d + lid * 2));
    float s = v.x * as.x + v.y * as.y;
    float d = v.x * ad.x + v.y * ad.y;
    #pragma unroll
    for (int off = 16; off; off >>= 1) {
        s += __shfl_xor_sync(0xffffffffu, s, off);
        d += __shfl_xor_sync(0xffffffffu, d, off);
    }
    if (lid == 0) { g_as2[warp] = s; g_ad2[warp] = d; }
}

// ---------------- layer-2 gather/softmax/aggregate + bias + log_softmax ------
__global__ void gat2_kernel(const float* __restrict__ b2, float* __restrict__ out, int n) {
    int warp = (blockIdx.x * blockDim.x + threadIdx.x) >> 5;
    int lid = threadIdx.x & 31;
    if (warp >= n) return;
    int beg = g_rowptr[warp], end = g_rowptr[warp + 1];
    float adn = g_ad2[warp];

    float mxv = -1e30f;
    for (int e = beg + lid; e < end; e += 32) {
        int s = g_srcs[e];
        mxv = fmaxf(mxv, lrelu(__ldg(&g_as2[s]) + adn));
    }
    #pragma unroll
    for (int off = 16; off; off >>= 1)
        mxv = fmaxf(mxv, __shfl_xor_sync(0xffffffffu, mxv, off));

    float acc0 = 0.f, acc1 = 0.f, denom = 0.f;
    for (int e = beg; e < end; e++) {
        int s = g_srcs[e];
        float w = 0.f;
        if (lid == 0) {
            w = __expf(lrelu(__ldg(&g_as2[s]) + adn) - mxv);
            denom += w;
        }
        w = __shfl_sync(0xffffffffu, w, 0);
        float2 v = *(const float2*)&g_h2[(size_t)s * 64 + lid * 2];
        acc0 += w * v.x;
        acc1 += w * v.y;
    }
    denom = __shfl_sync(0xffffffffu, denom, 0);
    float inv = 1.f / (denom + 1e-16f);
    float o0 = acc0 * inv + __ldg(&b2[lid * 2]);
    float o1 = acc1 * inv + __ldg(&b2[lid * 2 + 1]);

    // log_softmax over the 64 values held by the warp
    float rm = fmaxf(o0, o1);
    #pragma unroll
    for (int off = 16; off; off >>= 1)
        rm = fmaxf(rm, __shfl_xor_sync(0xffffffffu, rm, off));
    float se = __expf(o0 - rm) + __expf(o1 - rm);
    #pragma unroll
    for (int off = 16; off; off >>= 1)
        se += __shfl_xor_sync(0xffffffffu, se, off);
    float lse = rm + __logf(se);

    float2 res;
    res.x = o0 - lse;
    res.y = o1 - lse;
    *(float2*)&out[(size_t)warp * 64 + lid * 2] = res;
}

// ---------------- launch ------------------------------------------------------
extern "C" void kernel_launch(void* const* d_in, const int* in_sizes, int n_in,
                              void* d_out, int out_size) {
    const float* x      = (const float*)d_in[0];
    const int*   ei     = (const int*)d_in[1];
    const float* W1     = (const float*)d_in[2];
    const float* att1_s = (const float*)d_in[3];
    const float* att1_d = (const float*)d_in[4];
    const float* b1     = (const float*)d_in[5];
    const float* W2     = (const float*)d_in[6];
    const float* att2_s = (const float*)d_in[7];
    const float* att2_d = (const float*)d_in[8];
    const float* b2     = (const float*)d_in[9];
    float* out = (float*)d_out;

    int n = in_sizes[0] / 256;   // nodes
    int e = in_sizes[1] / 2;     // edges

    // CSR build (by dst)
    zero_cnt_kernel<<<(n + 255) / 256, 256>>>(n);
    hist_kernel<<<(e + 255) / 256, 256>>>(ei, e);
    scan_kernel<<<1, 1024>>>(n);
    copy_fill_kernel<<<(n + 255) / 256, 256>>>(n);
    scatter_kernel<<<(e + 255) / 256, 256>>>(ei, e);

    // layer 1
    gemm1_kernel<<<(n + 63) / 64, 256>>>(x, W1, n);
    att1_kernel<<<(n * 8 + 255) / 256, 256>>>(att1_s, att1_d, n);
    gat1_kernel<<<(n + 7) / 8, 256>>>(b1, n);

    // layer 2
    gemm2_kernel<<<(n + 63) / 64, 256>>>(W2, n);
    att2_kernel<<<(n + 7) / 8, 256>>>(att2_s, att2_d, n);
    gat2_kernel<<<(n + 7) / 8, 256>>>(b2, out, n);
}

// round 2
// speedup vs baseline: 1.3415x; 1.3415x over previous
#include <cuda_runtime.h>
#include <math.h>

#define NMAX 100000
#define EMAX 1600000

// ---------------- scratch (device globals) -----------------------------------
__device__ float g_h1[NMAX * 128];
__device__ float g_as1[NMAX * 8];
__device__ float g_ad1[NMAX * 8];
__device__ float g_x2[NMAX * 128];
__device__ float g_h2[NMAX * 64];
__device__ float g_as2[NMAX];
__device__ float g_ad2[NMAX];
__device__ int   g_rowptr[NMAX + 1];
__device__ int   g_cnt[NMAX];
__device__ int   g_fill[NMAX];
__device__ int   g_srcs[EMAX];
__device__ int   g_bsum[512];
__device__ int   g_boff[512];

__device__ __forceinline__ float lrelu(float x) { return x > 0.f ? x : 0.2f * x; }
__device__ __forceinline__ float elu1(float x)  { return x > 0.f ? x : (__expf(x) - 1.f); }

// packed f32x2 helpers (sm_100+)
__device__ __forceinline__ unsigned long long pack2b(float x) {
    unsigned long long r;
    asm("mov.b64 %0, {%1, %1};" : "=l"(r) : "f"(x));
    return r;
}
__device__ __forceinline__ unsigned long long pack2f(float x, float y) {
    unsigned long long r;
    asm("mov.b64 %0, {%1, %2};" : "=l"(r) : "f"(x), "f"(y));
    return r;
}
__device__ __forceinline__ void ffma2(unsigned long long& d, unsigned long long a, unsigned long long b) {
    asm("fma.rn.f32x2 %0, %1, %2, %0;" : "+l"(d) : "l"(a), "l"(b));
}
__device__ __forceinline__ void unpack2(unsigned long long p, float& lo, float& hi) {
    asm("mov.b64 {%0, %1}, %2;" : "=f"(lo), "=f"(hi) : "l"(p));
}

// ---------------- CSR build ---------------------------------------------------
__global__ void zero_cnt_kernel(int n) {
    int i = blockIdx.x * blockDim.x + threadIdx.x;
    if (i < n) g_cnt[i] = 0;
}

__global__ void hist_kernel(const int* __restrict__ ei, int e) {
    int i = blockIdx.x * blockDim.x + threadIdx.x;
    if (i < e) atomicAdd(&g_cnt[ei[e + i]], 1);
}

// phase 1: per-block inclusive scan (block size 1024); block totals to g_bsum
__global__ void scan1_kernel(int n) {
    __shared__ int wsum[32];
    int t = threadIdx.x, lane = t & 31, wid = t >> 5;
    int i = blockIdx.x * 1024 + t;
    int v = (i < n) ? g_cnt[i] : 0;
    int x = v;
    #pragma unroll
    for (int off = 1; off < 32; off <<= 1) {
        int u = __shfl_up_sync(0xffffffffu, x, off);
        if (lane >= off) x += u;
    }
    if (lane == 31) wsum[wid] = x;
    __syncthreads();
    if (wid == 0) {
        int s = wsum[lane];
        #pragma unroll
        for (int off = 1; off < 32; off <<= 1) {
            int u = __shfl_up_sync(0xffffffffu, s, off);
            if (lane >= off) s += u;
        }
        wsum[lane] = s;
    }
    __syncthreads();
    int incl = x + (wid ? wsum[wid - 1] : 0);
    if (i < n) g_rowptr[i + 1] = incl;          // local (no block offset yet)
    if (t == 1023) g_bsum[blockIdx.x] = incl;   // block total
}

// phase 2: single block exclusive scan of block totals
__global__ void scan2_kernel(int nb) {
    __shared__ int wsum[32];
    int t = threadIdx.x, lane = t & 31, wid = t >> 5;
    int v = (t < nb) ? g_bsum[t] : 0;
    int x = v;
    #pragma unroll
    for (int off = 1; off < 32; off <<= 1) {
        int u = __shfl_up_sync(0xffffffffu, x, off);
        if (lane >= off) x += u;
    }
    if (lane == 31) wsum[wid] = x;
    __syncthreads();
    if (wid == 0) {
        int s = wsum[lane];
        #pragma unroll
        for (int off = 1; off < 32; off <<= 1) {
            int u = __shfl_up_sync(0xffffffffu, s, off);
            if (lane >= off) s += u;
        }
        wsum[lane] = s;
    }
    __syncthreads();
    int incl = x + (wid ? wsum[wid - 1] : 0);
    if (t < nb) g_boff[t] = incl - v;           // exclusive
    if (t == 0) g_rowptr[0] = 0;
}

// phase 3: add block offsets; also produce g_fill (= exclusive prefix)
__global__ void scan3_kernel(int n) {
    int i = blockIdx.x * 1024 + threadIdx.x;
    if (i < n) {
        int fin = g_rowptr[i + 1] + g_boff[blockIdx.x];
        g_rowptr[i + 1] = fin;
        g_fill[i] = fin - g_cnt[i];
    }
}

__global__ void scatter_kernel(const int* __restrict__ ei, int e) {
    int i = blockIdx.x * blockDim.x + threadIdx.x;
    if (i < e) {
        int s = ei[i];
        int d = ei[e + i];
        int pos = atomicAdd(&g_fill[d], 1);
        g_srcs[pos] = s;
    }
}

// ---------------- GEMM1: h1 = x @ W1 (K=256, N=128), f32x2 packed -------------
__global__ void gemm1_kernel(const float* __restrict__ A, const float* __restrict__ B, int M) {
    const int K = 256, NC = 128;
    __shared__ float As[32][65];
    __shared__ float Bs[32][128];
    int tid = threadIdx.x;
    int blockRow = blockIdx.x * 64;
    int aRow = tid >> 3;
    int aCol = (tid & 7) << 2;
    int bRow = tid >> 5;
    int bCol = (tid & 31) << 2;
    int tRow = (tid >> 4) << 2;   // 4 rows
    int tCol = (tid & 15) << 3;   // 8 cols -> 4 packed pairs
    unsigned long long acc[4][4];
    #pragma unroll
    for (int i = 0; i < 4; i++)
        #pragma unroll
        for (int j = 0; j < 4; j++) acc[i][j] = 0ull;

    for (int k0 = 0; k0 < K; k0 += 32) {
        #pragma unroll
        for (int r = 0; r < 2; r++) {
            int row = blockRow + aRow + r * 32;
            float4 v = (row < M) ? *(const float4*)(A + (size_t)row * K + k0 + aCol)
                                 : make_float4(0.f, 0.f, 0.f, 0.f);
            As[aCol + 0][aRow + r * 32] = v.x;
            As[aCol + 1][aRow + r * 32] = v.y;
            As[aCol + 2][aRow + r * 32] = v.z;
            As[aCol + 3][aRow + r * 32] = v.w;
        }
        #pragma unroll
        for (int r = 0; r < 4; r++) {
            int row = bRow + r * 8;
            *(float4*)&Bs[row][bCol] = *(const float4*)(B + (size_t)(k0 + row) * NC + bCol);
        }
        __syncthreads();
        #pragma unroll
        for (int k = 0; k < 32; k++) {
            unsigned long long ap[4];
            ap[0] = pack2b(As[k][tRow]);
            ap[1] = pack2b(As[k][tRow + 1]);
            ap[2] = pack2b(As[k][tRow + 2]);
            ap[3] = pack2b(As[k][tRow + 3]);
            float4 bv0 = *(float4*)&Bs[k][tCol];
            float4 bv1 = *(float4*)&Bs[k][tCol + 4];
            unsigned long long bp[4];
            bp[0] = pack2f(bv0.x, bv0.y);
            bp[1] = pack2f(bv0.z, bv0.w);
            bp[2] = pack2f(bv1.x, bv1.y);
            bp[3] = pack2f(bv1.z, bv1.w);
            #pragma unroll
            for (int i = 0; i < 4; i++)
                #pragma unroll
                for (int j = 0; j < 4; j++) ffma2(acc[i][j], ap[i], bp[j]);
        }
        __syncthreads();
    }
    #pragma unroll
    for (int i = 0; i < 4; i++) {
        int row = blockRow + tRow + i;
        if (row < M) {
            float o[8];
            #pragma unroll
            for (int j = 0; j < 4; j++) unpack2(acc[i][j], o[2 * j], o[2 * j + 1]);
            *(float4*)&g_h1[(size_t)row * 128 + tCol]     = make_float4(o[0], o[1], o[2], o[3]);
            *(float4*)&g_h1[(size_t)row * 128 + tCol + 4] = make_float4(o[4], o[5], o[6], o[7]);
        }
    }
}

// ---------------- attention coefficients, layer 1 ----------------------------
__global__ void att1_kernel(const float* __restrict__ att_s, const float* __restrict__ att_d, int n) {
    int idx = blockIdx.x * blockDim.x + threadIdx.x;
    if (idx >= n * 8) return;
    int node = idx >> 3, h = idx & 7;
    const float4* hp = (const float4*)&g_h1[(size_t)node * 128 + h * 16];
    const float4* sp = (const float4*)&att_s[h * 16];
    const float4* dp = (const float4*)&att_d[h * 16];
    float s = 0.f, d = 0.f;
    #pragma unroll
    for (int q = 0; q < 4; q++) {
        float4 v = hp[q];
        float4 a = __ldg(&sp[q]);
        float4 b = __ldg(&dp[q]);
        s += v.x * a.x + v.y * a.y + v.z * a.z + v.w * a.w;
        d += v.x * b.x + v.y * b.y + v.z * b.z + v.w * b.w;
    }
    g_as1[idx] = s;
    g_ad1[idx] = d;
}

// ---------------- layer-1 gather (no max pass; softmax shift-invariant) ------
// one warp per dst node; lane owns channels [4*lid,4*lid+4); head = lid>>2
__global__ void gat1_kernel(const float* __restrict__ b1, int n) {
    int warp = (blockIdx.x * blockDim.x + threadIdx.x) >> 5;
    int lid = threadIdx.x & 31;
    if (warp >= n) return;
    int beg = g_rowptr[warp], end = g_rowptr[warp + 1];

    float adl = (lid < 8) ? g_ad1[warp * 8 + lid] : 0.f;
    int h = lid >> 2;
    float acc0 = 0.f, acc1 = 0.f, acc2 = 0.f, acc3 = 0.f;
    float denom = 0.f;

    int e = beg;
    for (; e + 1 < end; e += 2) {
        int s0 = g_srcs[e];
        int s1 = g_srcs[e + 1];
        float4 v0 = *(const float4*)&g_h1[(size_t)s0 * 128 + lid * 4];
        float4 v1 = *(const float4*)&g_h1[(size_t)s1 * 128 + lid * 4];
        float w0 = 0.f, w1 = 0.f;
        if (lid < 8) {
            w0 = __expf(lrelu(__ldg(&g_as1[s0 * 8 + lid]) + adl));
            w1 = __expf(lrelu(__ldg(&g_as1[s1 * 8 + lid]) + adl));
            denom += w0 + w1;
        }
        float wh0 = __shfl_sync(0xffffffffu, w0, h);
        float wh1 = __shfl_sync(0xffffffffu, w1, h);
        acc0 += wh0 * v0.x + wh1 * v1.x;
        acc1 += wh0 * v0.y + wh1 * v1.y;
        acc2 += wh0 * v0.z + wh1 * v1.z;
        acc3 += wh0 * v0.w + wh1 * v1.w;
    }
    if (e < end) {
        int s0 = g_srcs[e];
        float4 v0 = *(const float4*)&g_h1[(size_t)s0 * 128 + lid * 4];
        float w0 = 0.f;
        if (lid < 8) {
            w0 = __expf(lrelu(__ldg(&g_as1[s0 * 8 + lid]) + adl));
            denom += w0;
        }
        float wh0 = __shfl_sync(0xffffffffu, w0, h);
        acc0 += wh0 * v0.x;
        acc1 += wh0 * v0.y;
        acc2 += wh0 * v0.z;
        acc3 += wh0 * v0.w;
    }
    float dh = __shfl_sync(0xffffffffu, denom, h);
    float inv = 1.f / (dh + 1e-16f);
    float4 bb = *(const float4*)&b1[lid * 4];
    float4 o;
    o.x = elu1(acc0 * inv + bb.x);
    o.y = elu1(acc1 * inv + bb.y);
    o.z = elu1(acc2 * inv + bb.z);
    o.w = elu1(acc3 * inv + bb.w);
    *(float4*)&g_x2[(size_t)warp * 128 + lid * 4] = o;
}

// ---------------- GEMM2: h2 = x2 @ W2 (K=128, N=64), f32x2 packed -------------
__global__ void gemm2_kernel(const float* __restrict__ B, int M) {
    const int K = 128, NC = 64;
    __shared__ float As[32][65];
    __shared__ float Bs[32][64];
    int tid = threadIdx.x;
    int blockRow = blockIdx.x * 64;
    int aRow = tid >> 3;
    int aCol = (tid & 7) << 2;
    int bRow = tid >> 4;
    int bCol = (tid & 15) << 2;
    int tRow = (tid >> 4) << 2;
    int tCol = (tid & 15) << 2;    // 4 cols -> 2 packed pairs
    const float* A = g_x2;
    unsigned long long acc[4][2];
    #pragma unroll
    for (int i = 0; i < 4; i++) { acc[i][0] = 0ull; acc[i][1] = 0ull; }

    for (int k0 = 0; k0 < K; k0 += 32) {
        #pragma unroll
        for (int r = 0; r < 2; r++) {
            int row = blockRow + aRow + r * 32;
            float4 v = (row < M) ? *(const float4*)(A + (size_t)row * K + k0 + aCol)
                                 : make_float4(0.f, 0.f, 0.f, 0.f);
            As[aCol + 0][aRow + r * 32] = v.x;
            As[aCol + 1][aRow + r * 32] = v.y;
            As[aCol + 2][aRow + r * 32] = v.z;
            As[aCol + 3][aRow + r * 32] = v.w;
        }
        #pragma unroll
        for (int r = 0; r < 2; r++) {
            int row = bRow + r * 16;
            *(float4*)&Bs[row][bCol] = *(const float4*)(B + (size_t)(k0 + row) * NC + bCol);
        }
        __syncthreads();
        #pragma unroll
        for (int k = 0; k < 32; k++) {
            unsigned long long ap[4];
            ap[0] = pack2b(As[k][tRow]);
            ap[1] = pack2b(As[k][tRow + 1]);
            ap[2] = pack2b(As[k][tRow + 2]);
            ap[3] = pack2b(As[k][tRow + 3]);
            float4 bv = *(float4*)&Bs[k][tCol];
            unsigned long long bp0 = pack2f(bv.x, bv.y);
            unsigned long long bp1 = pack2f(bv.z, bv.w);
            #pragma unroll
            for (int i = 0; i < 4; i++) { ffma2(acc[i][0], ap[i], bp0); ffma2(acc[i][1], ap[i], bp1); }
        }
        __syncthreads();
    }
    #pragma unroll
    for (int i = 0; i < 4; i++) {
        int row = blockRow + tRow + i;
        if (row < M) {
            float o[4];
            unpack2(acc[i][0], o[0], o[1]);
            unpack2(acc[i][1], o[2], o[3]);
            *(float4*)&g_h2[(size_t)row * 64 + tCol] = make_float4(o[0], o[1], o[2], o[3]);
        }
    }
}

// ---------------- attention coefficients, layer 2 ----------------------------
__global__ void att2_kernel(const float* __restrict__ att_s, const float* __restrict__ att_d, int n) {
    int warp = (blockIdx.x * blockDim.x + threadIdx.x) >> 5;
    int lid = threadIdx.x & 31;
    if (warp >= n) return;
    float2 v = *(const float2*)&g_h2[(size_t)warp * 64 + lid * 2];
    float2 as = __ldg((const float2*)(att_s + lid * 2));
    float2 ad = __ldg((const float2*)(att_d + lid * 2));
    float s = v.x * as.x + v.y * as.y;
    float d = v.x * ad.x + v.y * ad.y;
    #pragma unroll
    for (int off = 16; off; off >>= 1) {
        s += __shfl_xor_sync(0xffffffffu, s, off);
        d += __shfl_xor_sync(0xffffffffu, d, off);
    }
    if (lid == 0) { g_as2[warp] = s; g_ad2[warp] = d; }
}

// ---------------- layer-2 gather + bias + log_softmax (no max pass) ----------
__global__ void gat2_kernel(const float* __restrict__ b2, float* __restrict__ out, int n) {
    int warp = (blockIdx.x * blockDim.x + threadIdx.x) >> 5;
    int lid = threadIdx.x & 31;
    if (warp >= n) return;
    int beg = g_rowptr[warp], end = g_rowptr[warp + 1];
    float adn = g_ad2[warp];

    float acc0 = 0.f, acc1 = 0.f, denom = 0.f;
    int e = beg;
    for (; e + 1 < end; e += 2) {
        int s0 = g_srcs[e];
        int s1 = g_srcs[e + 1];
        float2 v0 = *(const float2*)&g_h2[(size_t)s0 * 64 + lid * 2];
        float2 v1 = *(const float2*)&g_h2[(size_t)s1 * 64 + lid * 2];
        float w = 0.f;
        if (lid < 2) {
            int ss = lid ? s1 : s0;
            w = __expf(lrelu(__ldg(&g_as2[ss]) + adn));
            denom += w;
        }
        float w0 = __shfl_sync(0xffffffffu, w, 0);
        float w1 = __shfl_sync(0xffffffffu, w, 1);
        acc0 += w0 * v0.x + w1 * v1.x;
        acc1 += w0 * v0.y + w1 * v1.y;
    }
    if (e < end) {
        int s0 = g_srcs[e];
        float2 v0 = *(const float2*)&g_h2[(size_t)s0 * 64 + lid * 2];
        float w = 0.f;
        if (lid == 0) {
            w = __expf(lrelu(__ldg(&g_as2[s0]) + adn));
            denom += w;
        }
        float w0 = __shfl_sync(0xffffffffu, w, 0);
        acc0 += w0 * v0.x;
        acc1 += w0 * v0.y;
    }
    float dt = __shfl_sync(0xffffffffu, denom, 0) + __shfl_sync(0xffffffffu, denom, 1);
    float inv = 1.f / (dt + 1e-16f);
    float o0 = acc0 * inv + __ldg(&b2[lid * 2]);
    float o1 = acc1 * inv + __ldg(&b2[lid * 2 + 1]);

    float rm = fmaxf(o0, o1);
    #pragma unroll
    for (int off = 16; off; off >>= 1)
        rm = fmaxf(rm, __shfl_xor_sync(0xffffffffu, rm, off));
    float se = __expf(o0 - rm) + __expf(o1 - rm);
    #pragma unroll
    for (int off = 16; off; off >>= 1)
        se += __shfl_xor_sync(0xffffffffu, se, off);
    float lse = rm + __logf(se);

    float2 res;
    res.x = o0 - lse;
    res.y = o1 - lse;
    *(float2*)&out[(size_t)warp * 64 + lid * 2] = res;
}

// ---------------- launch ------------------------------------------------------
extern "C" void kernel_launch(void* const* d_in, const int* in_sizes, int n_in,
                              void* d_out, int out_size) {
    const float* x      = (const float*)d_in[0];
    const int*   ei     = (const int*)d_in[1];
    const float* W1     = (const float*)d_in[2];
    const float* att1_s = (const float*)d_in[3];
    const float* att1_d = (const float*)d_in[4];
    const float* b1     = (const float*)d_in[5];
    const float* W2     = (const float*)d_in[6];
    const float* att2_s = (const float*)d_in[7];
    const float* att2_d = (const float*)d_in[8];
    const float* b2     = (const float*)d_in[9];
    float* out = (float*)d_out;

    int n = in_sizes[0] / 256;
    int e = in_sizes[1] / 2;
    int nb = (n + 1023) / 1024;

    // CSR build (by dst)
    zero_cnt_kernel<<<(n + 255) / 256, 256>>>(n);
    hist_kernel<<<(e + 255) / 256, 256>>>(ei, e);
    scan1_kernel<<<nb, 1024>>>(n);
    scan2_kernel<<<1, 512>>>(nb);
    scan3_kernel<<<nb, 1024>>>(n);
    scatter_kernel<<<(e + 255) / 256, 256>>>(ei, e);

    // layer 1
    gemm1_kernel<<<(n + 63) / 64, 256>>>(x, W1, n);
    att1_kernel<<<(n * 8 + 255) / 256, 256>>>(att1_s, att1_d, n);
    gat1_kernel<<<(n + 7) / 8, 256>>>(b1, n);

    // layer 2
    gemm2_kernel<<<(n + 63) / 64, 256>>>(W2, n);
    att2_kernel<<<(n + 7) / 8, 256>>>(att2_s, att2_d, n);
    gat2_kernel<<<(n + 7) / 8, 256>>>(b2, out, n);
}

// round 3
// speedup vs baseline: 1.4018x; 1.0450x over previous
#include <cuda_runtime.h>
#include <math.h>

#define NMAX 100000
#define EMAX 1600000

// ---------------- scratch (device globals) -----------------------------------
__device__ float g_h1[NMAX * 128];
__device__ float g_as1[NMAX * 8];
__device__ float g_ad1[NMAX * 8];
__device__ float g_x2[NMAX * 128];
__device__ float g_h2[NMAX * 64];
__device__ float g_as2[NMAX];
__device__ float g_ad2[NMAX];
__device__ int   g_rowptr[NMAX + 1];
__device__ int   g_cnt[NMAX];
__device__ int   g_fill[NMAX];
__device__ int   g_srcs[EMAX];
__device__ int   g_bsum[512];
__device__ int   g_boff[512];

__device__ __forceinline__ float lrelu(float x) { return x > 0.f ? x : 0.2f * x; }
__device__ __forceinline__ float elu1(float x)  { return x > 0.f ? x : (__expf(x) - 1.f); }

// packed f32x2 helpers (sm_100+)
__device__ __forceinline__ unsigned long long pack2b(float x) {
    unsigned long long r;
    asm("mov.b64 %0, {%1, %1};" : "=l"(r) : "f"(x));
    return r;
}
__device__ __forceinline__ unsigned long long pack2f(float x, float y) {
    unsigned long long r;
    asm("mov.b64 %0, {%1, %2};" : "=l"(r) : "f"(x), "f"(y));
    return r;
}
__device__ __forceinline__ void ffma2(unsigned long long& d, unsigned long long a, unsigned long long b) {
    asm("fma.rn.f32x2 %0, %1, %2, %0;" : "+l"(d) : "l"(a), "l"(b));
}
__device__ __forceinline__ void unpack2(unsigned long long p, float& lo, float& hi) {
    asm("mov.b64 {%0, %1}, %2;" : "=f"(lo), "=f"(hi) : "l"(p));
}

// ---------------- CSR build ---------------------------------------------------
__global__ void zero_cnt_kernel(int n) {
    int i = blockIdx.x * blockDim.x + threadIdx.x;
    if (i < n) g_cnt[i] = 0;
}

__global__ void hist_kernel(const int* __restrict__ ei, int e) {
    int i = blockIdx.x * blockDim.x + threadIdx.x;
    if (i < e) atomicAdd(&g_cnt[ei[e + i]], 1);
}

__global__ void scan1_kernel(int n) {
    __shared__ int wsum[32];
    int t = threadIdx.x, lane = t & 31, wid = t >> 5;
    int i = blockIdx.x * 1024 + t;
    int v = (i < n) ? g_cnt[i] : 0;
    int x = v;
    #pragma unroll
    for (int off = 1; off < 32; off <<= 1) {
        int u = __shfl_up_sync(0xffffffffu, x, off);
        if (lane >= off) x += u;
    }
    if (lane == 31) wsum[wid] = x;
    __syncthreads();
    if (wid == 0) {
        int s = wsum[lane];
        #pragma unroll
        for (int off = 1; off < 32; off <<= 1) {
            int u = __shfl_up_sync(0xffffffffu, s, off);
            if (lane >= off) s += u;
        }
        wsum[lane] = s;
    }
    __syncthreads();
    int incl = x + (wid ? wsum[wid - 1] : 0);
    if (i < n) g_rowptr[i + 1] = incl;
    if (t == 1023) g_bsum[blockIdx.x] = incl;
}

__global__ void scan2_kernel(int nb) {
    __shared__ int wsum[32];
    int t = threadIdx.x, lane = t & 31, wid = t >> 5;
    int v = (t < nb) ? g_bsum[t] : 0;
    int x = v;
    #pragma unroll
    for (int off = 1; off < 32; off <<= 1) {
        int u = __shfl_up_sync(0xffffffffu, x, off);
        if (lane >= off) x += u;
    }
    if (lane == 31) wsum[wid] = x;
    __syncthreads();
    if (wid == 0) {
        int s = wsum[lane];
        #pragma unroll
        for (int off = 1; off < 32; off <<= 1) {
            int u = __shfl_up_sync(0xffffffffu, s, off);
            if (lane >= off) s += u;
        }
        wsum[lane] = s;
    }
    __syncthreads();
    int incl = x + (wid ? wsum[wid - 1] : 0);
    if (t < nb) g_boff[t] = incl - v;
    if (t == 0) g_rowptr[0] = 0;
}

__global__ void scan3_kernel(int n) {
    int i = blockIdx.x * 1024 + threadIdx.x;
    if (i < n) {
        int fin = g_rowptr[i + 1] + g_boff[blockIdx.x];
        g_rowptr[i + 1] = fin;
        g_fill[i] = fin - g_cnt[i];
    }
}

__global__ void scatter_kernel(const int* __restrict__ ei, int e) {
    int i = blockIdx.x * blockDim.x + threadIdx.x;
    if (i < e) {
        int s = ei[i];
        int d = ei[e + i];
        int pos = atomicAdd(&g_fill[d], 1);
        g_srcs[pos] = s;
    }
}

// ---------------- GEMM1: h1 = x @ W1 (K=256, N=128), f32x2 packed -------------
__global__ void gemm1_kernel(const float* __restrict__ A, const float* __restrict__ B, int M) {
    const int K = 256, NC = 128;
    __shared__ float As[32][65];
    __shared__ float Bs[32][128];
    int tid = threadIdx.x;
    int blockRow = blockIdx.x * 64;
    int aRow = tid >> 3;
    int aCol = (tid & 7) << 2;
    int bRow = tid >> 5;
    int bCol = (tid & 31) << 2;
    int tRow = (tid >> 4) << 2;
    int tCol = (tid & 15) << 3;
    unsigned long long acc[4][4];
    #pragma unroll
    for (int i = 0; i < 4; i++)
        #pragma unroll
        for (int j = 0; j < 4; j++) acc[i][j] = 0ull;

    for (int k0 = 0; k0 < K; k0 += 32) {
        #pragma unroll
        for (int r = 0; r < 2; r++) {
            int row = blockRow + aRow + r * 32;
            float4 v = (row < M) ? *(const float4*)(A + (size_t)row * K + k0 + aCol)
                                 : make_float4(0.f, 0.f, 0.f, 0.f);
            As[aCol + 0][aRow + r * 32] = v.x;
            As[aCol + 1][aRow + r * 32] = v.y;
            As[aCol + 2][aRow + r * 32] = v.z;
            As[aCol + 3][aRow + r * 32] = v.w;
        }
        #pragma unroll
        for (int r = 0; r < 4; r++) {
            int row = bRow + r * 8;
            *(float4*)&Bs[row][bCol] = *(const float4*)(B + (size_t)(k0 + row) * NC + bCol);
        }
        __syncthreads();
        #pragma unroll
        for (int k = 0; k < 32; k++) {
            unsigned long long ap[4];
            ap[0] = pack2b(As[k][tRow]);
            ap[1] = pack2b(As[k][tRow + 1]);
            ap[2] = pack2b(As[k][tRow + 2]);
            ap[3] = pack2b(As[k][tRow + 3]);
            float4 bv0 = *(float4*)&Bs[k][tCol];
            float4 bv1 = *(float4*)&Bs[k][tCol + 4];
            unsigned long long bp[4];
            bp[0] = pack2f(bv0.x, bv0.y);
            bp[1] = pack2f(bv0.z, bv0.w);
            bp[2] = pack2f(bv1.x, bv1.y);
            bp[3] = pack2f(bv1.z, bv1.w);
            #pragma unroll
            for (int i = 0; i < 4; i++)
                #pragma unroll
                for (int j = 0; j < 4; j++) ffma2(acc[i][j], ap[i], bp[j]);
        }
        __syncthreads();
    }
    #pragma unroll
    for (int i = 0; i < 4; i++) {
        int row = blockRow + tRow + i;
        if (row < M) {
            float o[8];
            #pragma unroll
            for (int j = 0; j < 4; j++) unpack2(acc[i][j], o[2 * j], o[2 * j + 1]);
            *(float4*)&g_h1[(size_t)row * 128 + tCol]     = make_float4(o[0], o[1], o[2], o[3]);
            *(float4*)&g_h1[(size_t)row * 128 + tCol + 4] = make_float4(o[4], o[5], o[6], o[7]);
        }
    }
}

// ---------------- attention coefficients, layer 1 ----------------------------
__global__ void att1_kernel(const float* __restrict__ att_s, const float* __restrict__ att_d, int n) {
    int idx = blockIdx.x * blockDim.x + threadIdx.x;
    if (idx >= n * 8) return;
    int node = idx >> 3, h = idx & 7;
    const float4* hp = (const float4*)&g_h1[(size_t)node * 128 + h * 16];
    const float4* sp = (const float4*)&att_s[h * 16];
    const float4* dp = (const float4*)&att_d[h * 16];
    float s = 0.f, d = 0.f;
    #pragma unroll
    for (int q = 0; q < 4; q++) {
        float4 v = hp[q];
        float4 a = __ldg(&sp[q]);
        float4 b = __ldg(&dp[q]);
        s += v.x * a.x + v.y * a.y + v.z * a.z + v.w * a.w;
        d += v.x * b.x + v.y * b.y + v.z * b.z + v.w * b.w;
    }
    g_as1[idx] = s;
    g_ad1[idx] = d;
}

// ---------------- layer-1 gather (4 edges per step, warp per node) -----------
__global__ void gat1_kernel(const float* __restrict__ b1, int n) {
    int warp = (blockIdx.x * blockDim.x + threadIdx.x) >> 5;
    int lid = threadIdx.x & 31;
    if (warp >= n) return;
    int beg = g_rowptr[warp], end = g_rowptr[warp + 1];
    int h  = lid >> 2;          // head for channel accumulation
    int eo = lid >> 3;          // edge-offset 0..3 in weight phase
    int hh = lid & 7;           // head in weight phase
    float adl = g_ad1[warp * 8 + hh];
    float4 acc = make_float4(0.f, 0.f, 0.f, 0.f);
    float dpart = 0.f;

    for (int base = beg; base < end; base += 32) {
        int cnt = end - base; if (cnt > 32) cnt = 32;
        int sidx = (base + lid < end) ? __ldg(&g_srcs[base + lid]) : 0;
        for (int g = 0; g < cnt; g += 4) {
            int sj = __shfl_sync(0xffffffffu, sidx, g + eo);
            float w = 0.f;
            if (g + eo < cnt)
                w = __expf(lrelu(__ldg(&g_as1[sj * 8 + hh]) + adl));
            dpart += w;
            #pragma unroll
            for (int q = 0; q < 4; q++) {
                float wq = __shfl_sync(0xffffffffu, w, q * 8 + h);
                int   sq = __shfl_sync(0xffffffffu, sidx, g + q);
                float4 v = *(const float4*)&g_h1[(size_t)sq * 128 + lid * 4];
                acc.x += wq * v.x;
                acc.y += wq * v.y;
                acc.z += wq * v.z;
                acc.w += wq * v.w;
            }
        }
    }
    // reduce denominators over the 4 edge-offset groups (xor 8, 16)
    float dsum = dpart;
    dsum += __shfl_xor_sync(0xffffffffu, dsum, 8);
    dsum += __shfl_xor_sync(0xffffffffu, dsum, 16);
    float dh = __shfl_sync(0xffffffffu, dsum, h);   // lane h holds head h's denom
    float inv = 1.f / (dh + 1e-16f);
    float4 bb = *(const float4*)&b1[lid * 4];
    float4 o;
    o.x = elu1(acc.x * inv + bb.x);
    o.y = elu1(acc.y * inv + bb.y);
    o.z = elu1(acc.z * inv + bb.z);
    o.w = elu1(acc.w * inv + bb.w);
    *(float4*)&g_x2[(size_t)warp * 128 + lid * 4] = o;
}

// ---------------- GEMM2: h2 = x2 @ W2 (K=128, N=64), f32x2 packed -------------
__global__ void gemm2_kernel(const float* __restrict__ B, int M) {
    const int K = 128, NC = 64;
    __shared__ float As[32][65];
    __shared__ float Bs[32][64];
    int tid = threadIdx.x;
    int blockRow = blockIdx.x * 64;
    int aRow = tid >> 3;
    int aCol = (tid & 7) << 2;
    int bRow = tid >> 4;
    int bCol = (tid & 15) << 2;
    int tRow = (tid >> 4) << 2;
    int tCol = (tid & 15) << 2;
    const float* A = g_x2;
    unsigned long long acc[4][2];
    #pragma unroll
    for (int i = 0; i < 4; i++) { acc[i][0] = 0ull; acc[i][1] = 0ull; }

    for (int k0 = 0; k0 < K; k0 += 32) {
        #pragma unroll
        for (int r = 0; r < 2; r++) {
            int row = blockRow + aRow + r * 32;
            float4 v = (row < M) ? *(const float4*)(A + (size_t)row * K + k0 + aCol)
                                 : make_float4(0.f, 0.f, 0.f, 0.f);
            As[aCol + 0][aRow + r * 32] = v.x;
            As[aCol + 1][aRow + r * 32] = v.y;
            As[aCol + 2][aRow + r * 32] = v.z;
            As[aCol + 3][aRow + r * 32] = v.w;
        }
        #pragma unroll
        for (int r = 0; r < 2; r++) {
            int row = bRow + r * 16;
            *(float4*)&Bs[row][bCol] = *(const float4*)(B + (size_t)(k0 + row) * NC + bCol);
        }
        __syncthreads();
        #pragma unroll
        for (int k = 0; k < 32; k++) {
            unsigned long long ap[4];
            ap[0] = pack2b(As[k][tRow]);
            ap[1] = pack2b(As[k][tRow + 1]);
            ap[2] = pack2b(As[k][tRow + 2]);
            ap[3] = pack2b(As[k][tRow + 3]);
            float4 bv = *(float4*)&Bs[k][tCol];
            unsigned long long bp0 = pack2f(bv.x, bv.y);
            unsigned long long bp1 = pack2f(bv.z, bv.w);
            #pragma unroll
            for (int i = 0; i < 4; i++) { ffma2(acc[i][0], ap[i], bp0); ffma2(acc[i][1], ap[i], bp1); }
        }
        __syncthreads();
    }
    #pragma unroll
    for (int i = 0; i < 4; i++) {
        int row = blockRow + tRow + i;
        if (row < M) {
            float o[4];
            unpack2(acc[i][0], o[0], o[1]);
            unpack2(acc[i][1], o[2], o[3]);
            *(float4*)&g_h2[(size_t)row * 64 + tCol] = make_float4(o[0], o[1], o[2], o[3]);
        }
    }
}

// ---------------- attention coefficients, layer 2 ----------------------------
__global__ void att2_kernel(const float* __restrict__ att_s, const float* __restrict__ att_d, int n) {
    int warp = (blockIdx.x * blockDim.x + threadIdx.x) >> 5;
    int lid = threadIdx.x & 31;
    if (warp >= n) return;
    float2 v = *(const float2*)&g_h2[(size_t)warp * 64 + lid * 2];
    float2 as = __ldg((const float2*)(att_s + lid * 2));
    float2 ad = __ldg((const float2*)(att_d + lid * 2));
    float s = v.x * as.x + v.y * as.y;
    float d = v.x * ad.x + v.y * ad.y;
    #pragma unroll
    for (int off = 16; off; off >>= 1) {
        s += __shfl_xor_sync(0xffffffffu, s, off);
        d += __shfl_xor_sync(0xffffffffu, d, off);
    }
    if (lid == 0) { g_as2[warp] = s; g_ad2[warp] = d; }
}

// ---------------- layer-2 gather (4 edges per step) + log_softmax ------------
__global__ void gat2_kernel(const float* __restrict__ b2, float* __restrict__ out, int n) {
    int warp = (blockIdx.x * blockDim.x + threadIdx.x) >> 5;
    int lid = threadIdx.x & 31;
    if (warp >= n) return;
    int beg = g_rowptr[warp], end = g_rowptr[warp + 1];
    float adn = g_ad2[warp];

    float acc0 = 0.f, acc1 = 0.f, dpart = 0.f;
    for (int base = beg; base < end; base += 32) {
        int cnt = end - base; if (cnt > 32) cnt = 32;
        int sidx = (base + lid < end) ? __ldg(&g_srcs[base + lid]) : 0;
        for (int g = 0; g < cnt; g += 4) {
            int widx = g + (lid & 3); if (widx > 31) widx = 31;
            int sj = __shfl_sync(0xffffffffu, sidx, widx);
            float w = 0.f;
            if (lid < 4 && g + lid < cnt)
                w = __expf(lrelu(__ldg(&g_as2[sj]) + adn));
            dpart += w;
            #pragma unroll
            for (int q = 0; q < 4; q++) {
                float wq = __shfl_sync(0xffffffffu, w, q);
                int   sq = __shfl_sync(0xffffffffu, sidx, g + q);
                float2 v = *(const float2*)&g_h2[(size_t)sq * 64 + lid * 2];
                acc0 += wq * v.x;
                acc1 += wq * v.y;
            }
        }
    }
    float dsum = dpart;
    dsum += __shfl_xor_sync(0xffffffffu, dsum, 1);
    dsum += __shfl_xor_sync(0xffffffffu, dsum, 2);
    float dt = __shfl_sync(0xffffffffu, dsum, 0);
    float inv = 1.f / (dt + 1e-16f);
    float o0 = acc0 * inv + __ldg(&b2[lid * 2]);
    float o1 = acc1 * inv + __ldg(&b2[lid * 2 + 1]);

    float rm = fmaxf(o0, o1);
    #pragma unroll
    for (int off = 16; off; off >>= 1)
        rm = fmaxf(rm, __shfl_xor_sync(0xffffffffu, rm, off));
    float se = __expf(o0 - rm) + __expf(o1 - rm);
    #pragma unroll
    for (int off = 16; off; off >>= 1)
        se += __shfl_xor_sync(0xffffffffu, se, off);
    float lse = rm + __logf(se);

    float2 res;
    res.x = o0 - lse;
    res.y = o1 - lse;
    *(float2*)&out[(size_t)warp * 64 + lid * 2] = res;
}

// ---------------- launch ------------------------------------------------------
extern "C" void kernel_launch(void* const* d_in, const int* in_sizes, int n_in,
                              void* d_out, int out_size) {
    const float* x      = (const float*)d_in[0];
    const int*   ei     = (const int*)d_in[1];
    const float* W1     = (const float*)d_in[2];
    const float* att1_s = (const float*)d_in[3];
    const float* att1_d = (const float*)d_in[4];
    const float* b1     = (const float*)d_in[5];
    const float* W2     = (const float*)d_in[6];
    const float* att2_s = (const float*)d_in[7];
    const float* att2_d = (const float*)d_in[8];
    const float* b2     = (const float*)d_in[9];
    float* out = (float*)d_out;

    int n = in_sizes[0] / 256;
    int e = in_sizes[1] / 2;
    int nb = (n + 1023) / 1024;

    // lazily created side stream + events (created on the eager correctness
    // call, before the harness captures; reused identically every call)
    static cudaStream_t s2 = nullptr;
    static cudaEvent_t evFork = nullptr, evJoin = nullptr;
    if (!s2) {
        cudaStreamCreateWithFlags(&s2, cudaStreamNonBlocking);
        cudaEventCreateWithFlags(&evFork, cudaEventDisableTiming);
        cudaEventCreateWithFlags(&evJoin, cudaEventDisableTiming);
    }

    // fork: gemm1 + att1 run concurrently with the CSR build
    cudaEventRecord(evFork, 0);
    cudaStreamWaitEvent(s2, evFork, 0);
    gemm1_kernel<<<(n + 63) / 64, 256, 0, s2>>>(x, W1, n);
    att1_kernel<<<(n * 8 + 255) / 256, 256, 0, s2>>>(att1_s, att1_d, n);
    cudaEventRecord(evJoin, s2);

    // CSR build (by dst) on the main stream
    zero_cnt_kernel<<<(n + 255) / 256, 256>>>(n);
    hist_kernel<<<(e + 255) / 256, 256>>>(ei, e);
    scan1_kernel<<<nb, 1024>>>(n);
    scan2_kernel<<<1, 512>>>(nb);
    scan3_kernel<<<nb, 1024>>>(n);
    scatter_kernel<<<(e + 255) / 256, 256>>>(ei, e);

    // join, then the dependent chain
    cudaStreamWaitEvent(0, evJoin, 0);
    gat1_kernel<<<(n + 7) / 8, 256>>>(b1, n);
    gemm2_kernel<<<(n + 63) / 64, 256>>>(W2, n);
    att2_kernel<<<(n + 7) / 8, 256>>>(att2_s, att2_d, n);
    gat2_kernel<<<(n + 7) / 8, 256>>>(b2, out, n);
}

// round 4
// speedup vs baseline: 1.5116x; 1.0783x over previous
#include <cuda_runtime.h>
#include <cuda_fp16.h>
#include <math.h>

#define NMAX 100000
#define EMAX 1600000

// ---------------- scratch (device globals) -----------------------------------
__device__ __half g_h1h[NMAX * 128];   // layer1 features, fp16 (gather payload)
__device__ __half g_h2h[NMAX * 64];    // layer2 features, fp16
__device__ float  g_as1[NMAX * 8];
__device__ float  g_ad1[NMAX * 8];
__device__ float  g_x2[NMAX * 128];    // elu(out1+b1), fp32 (gemm2 input)
__device__ float  g_as2[NMAX];
__device__ float  g_ad2[NMAX];
__device__ int    g_rowptr[NMAX + 1];
__device__ int    g_cnt[NMAX];
__device__ int    g_fill[NMAX];
__device__ int    g_srcs[EMAX];
__device__ int    g_bsum[512];
__device__ int    g_boff[512];

__device__ __forceinline__ float lrelu(float x) { return x > 0.f ? x : 0.2f * x; }
__device__ __forceinline__ float elu1(float x)  { return x > 0.f ? x : (__expf(x) - 1.f); }

// packed f32x2 helpers (sm_100+)
__device__ __forceinline__ unsigned long long pack2b(float x) {
    unsigned long long r;
    asm("mov.b64 %0, {%1, %1};" : "=l"(r) : "f"(x));
    return r;
}
__device__ __forceinline__ unsigned long long pack2f(float x, float y) {
    unsigned long long r;
    asm("mov.b64 %0, {%1, %2};" : "=l"(r) : "f"(x), "f"(y));
    return r;
}
__device__ __forceinline__ void ffma2(unsigned long long& d, unsigned long long a, unsigned long long b) {
    asm("fma.rn.f32x2 %0, %1, %2, %0;" : "+l"(d) : "l"(a), "l"(b));
}
__device__ __forceinline__ void unpack2(unsigned long long p, float& lo, float& hi) {
    asm("mov.b64 {%0, %1}, %2;" : "=f"(lo), "=f"(hi) : "l"(p));
}

// ---------------- CSR build ---------------------------------------------------
__global__ void zero_cnt_kernel(int n) {
    int i = blockIdx.x * blockDim.x + threadIdx.x;
    if (i < n) g_cnt[i] = 0;
}

__global__ void hist_kernel(const int* __restrict__ ei, int e) {
    int i = blockIdx.x * blockDim.x + threadIdx.x;
    if (i < e) atomicAdd(&g_cnt[ei[e + i]], 1);
}

__global__ void scan1_kernel(int n) {
    __shared__ int wsum[32];
    int t = threadIdx.x, lane = t & 31, wid = t >> 5;
    int i = blockIdx.x * 1024 + t;
    int v = (i < n) ? g_cnt[i] : 0;
    int x = v;
    #pragma unroll
    for (int off = 1; off < 32; off <<= 1) {
        int u = __shfl_up_sync(0xffffffffu, x, off);
        if (lane >= off) x += u;
    }
    if (lane == 31) wsum[wid] = x;
    __syncthreads();
    if (wid == 0) {
        int s = wsum[lane];
        #pragma unroll
        for (int off = 1; off < 32; off <<= 1) {
            int u = __shfl_up_sync(0xffffffffu, s, off);
            if (lane >= off) s += u;
        }
        wsum[lane] = s;
    }
    __syncthreads();
    int incl = x + (wid ? wsum[wid - 1] : 0);
    if (i < n) g_rowptr[i + 1] = incl;
    if (t == 1023) g_bsum[blockIdx.x] = incl;
}

__global__ void scan2_kernel(int nb) {
    __shared__ int wsum[32];
    int t = threadIdx.x, lane = t & 31, wid = t >> 5;
    int v = (t < nb) ? g_bsum[t] : 0;
    int x = v;
    #pragma unroll
    for (int off = 1; off < 32; off <<= 1) {
        int u = __shfl_up_sync(0xffffffffu, x, off);
        if (lane >= off) x += u;
    }
    if (lane == 31) wsum[wid] = x;
    __syncthreads();
    if (wid == 0) {
        int s = wsum[lane];
        #pragma unroll
        for (int off = 1; off < 32; off <<= 1) {
            int u = __shfl_up_sync(0xffffffffu, s, off);
            if (lane >= off) s += u;
        }
        wsum[lane] = s;
    }
    __syncthreads();
    int incl = x + (wid ? wsum[wid - 1] : 0);
    if (t < nb) g_boff[t] = incl - v;
    if (t == 0) g_rowptr[0] = 0;
}

__global__ void scan3_kernel(int n) {
    int i = blockIdx.x * 1024 + threadIdx.x;
    if (i < n) {
        int fin = g_rowptr[i + 1] + g_boff[blockIdx.x];
        g_rowptr[i + 1] = fin;
        g_fill[i] = fin - g_cnt[i];
    }
}

__global__ void scatter_kernel(const int* __restrict__ ei, int e) {
    int i = blockIdx.x * blockDim.x + threadIdx.x;
    if (i < e) {
        int s = ei[i];
        int d = ei[e + i];
        int pos = atomicAdd(&g_fill[d], 1);
        g_srcs[pos] = s;
    }
}

// ---------------- GEMM1 + att1 fold: h1h = fp16(x@W1); as1/ad1 ---------------
__global__ void gemm1_kernel(const float* __restrict__ A, const float* __restrict__ B,
                             const float* __restrict__ att_s, const float* __restrict__ att_d,
                             int M) {
    const int K = 256, NC = 128;
    __shared__ float As[32][65];
    __shared__ float Bs[32][128];
    int tid = threadIdx.x;
    int blockRow = blockIdx.x * 64;
    int aRow = tid >> 3;
    int aCol = (tid & 7) << 2;
    int bRow = tid >> 5;
    int bCol = (tid & 31) << 2;
    int tRow = (tid >> 4) << 2;   // 4 rows per thread
    int tCol = (tid & 15) << 3;   // 8 cols per thread
    unsigned long long acc[4][4];
    #pragma unroll
    for (int i = 0; i < 4; i++)
        #pragma unroll
        for (int j = 0; j < 4; j++) acc[i][j] = 0ull;

    for (int k0 = 0; k0 < K; k0 += 32) {
        #pragma unroll
        for (int r = 0; r < 2; r++) {
            int row = blockRow + aRow + r * 32;
            float4 v = (row < M) ? *(const float4*)(A + (size_t)row * K + k0 + aCol)
                                 : make_float4(0.f, 0.f, 0.f, 0.f);
            As[aCol + 0][aRow + r * 32] = v.x;
            As[aCol + 1][aRow + r * 32] = v.y;
            As[aCol + 2][aRow + r * 32] = v.z;
            As[aCol + 3][aRow + r * 32] = v.w;
        }
        #pragma unroll
        for (int r = 0; r < 4; r++) {
            int row = bRow + r * 8;
            *(float4*)&Bs[row][bCol] = *(const float4*)(B + (size_t)(k0 + row) * NC + bCol);
        }
        __syncthreads();
        #pragma unroll
        for (int k = 0; k < 32; k++) {
            unsigned long long ap[4];
            ap[0] = pack2b(As[k][tRow]);
            ap[1] = pack2b(As[k][tRow + 1]);
            ap[2] = pack2b(As[k][tRow + 2]);
            ap[3] = pack2b(As[k][tRow + 3]);
            float4 bv0 = *(float4*)&Bs[k][tCol];
            float4 bv1 = *(float4*)&Bs[k][tCol + 4];
            unsigned long long bp[4];
            bp[0] = pack2f(bv0.x, bv0.y);
            bp[1] = pack2f(bv0.z, bv0.w);
            bp[2] = pack2f(bv1.x, bv1.y);
            bp[3] = pack2f(bv1.z, bv1.w);
            #pragma unroll
            for (int i = 0; i < 4; i++)
                #pragma unroll
                for (int j = 0; j < 4; j++) ffma2(acc[i][j], ap[i], bp[j]);
        }
        __syncthreads();
    }

    // epilogue: write fp16 h1, compute attention partials + pair-reduce
    int hd = tCol >> 4;          // head (8 cols lie inside one 16-col head)
    int co = tCol & 15;          // 0 or 8 within head
    float as_v[8], ad_v[8];
    #pragma unroll
    for (int j = 0; j < 8; j++) {
        as_v[j] = __ldg(&att_s[hd * 16 + co + j]);
        ad_v[j] = __ldg(&att_d[hd * 16 + co + j]);
    }
    #pragma unroll
    for (int i = 0; i < 4; i++) {
        int row = blockRow + tRow + i;
        float o[8];
        #pragma unroll
        for (int j = 0; j < 4; j++) unpack2(acc[i][j], o[2 * j], o[2 * j + 1]);
        __half hb[8];
        #pragma unroll
        for (int j = 0; j < 8; j++) hb[j] = __float2half_rn(o[j]);
        float s = 0.f, d = 0.f;
        #pragma unroll
        for (int j = 0; j < 8; j++) { s += o[j] * as_v[j]; d += o[j] * ad_v[j]; }
        s += __shfl_xor_sync(0xffffffffu, s, 1);
        d += __shfl_xor_sync(0xffffffffu, d, 1);
        if (row < M) {
            *(uint4*)&g_h1h[(size_t)row * 128 + tCol] = *(uint4*)hb;
            if ((tid & 1) == 0) {
                g_as1[row * 8 + hd] = s;
                g_ad1[row * 8 + hd] = d;
            }
        }
    }
}

// ---------------- layer-1 gather (fp16 payload, warp per node) ---------------
__global__ void gat1_kernel(const float* __restrict__ b1, int n) {
    int warp = (blockIdx.x * blockDim.x + threadIdx.x) >> 5;
    int lid = threadIdx.x & 31;
    if (warp >= n) return;
    int beg = g_rowptr[warp], end = g_rowptr[warp + 1];
    int h  = lid >> 2;          // head for channel accumulation
    int eo = lid >> 3;          // edge-offset 0..3 in weight phase
    int hh = lid & 7;           // head in weight phase
    float adl = g_ad1[warp * 8 + hh];
    float4 acc = make_float4(0.f, 0.f, 0.f, 0.f);
    float dpart = 0.f;

    for (int base = beg; base < end; base += 32) {
        int cnt = end - base; if (cnt > 32) cnt = 32;
        int sidx = (base + lid < end) ? __ldg(&g_srcs[base + lid]) : 0;
        for (int g = 0; g < cnt; g += 4) {
            int sj = __shfl_sync(0xffffffffu, sidx, g + eo);
            float w = 0.f;
            if (g + eo < cnt)
                w = __expf(lrelu(__ldg(&g_as1[sj * 8 + hh]) + adl));
            dpart += w;
            #pragma unroll
            for (int q = 0; q < 4; q++) {
                float wq = __shfl_sync(0xffffffffu, w, q * 8 + h);
                int   sq = __shfl_sync(0xffffffffu, sidx, g + q);
                uint2 hv = *(const uint2*)&g_h1h[(size_t)sq * 128 + lid * 4];
                float2 f0 = __half22float2(*(__half2*)&hv.x);
                float2 f1 = __half22float2(*(__half2*)&hv.y);
                acc.x += wq * f0.x;
                acc.y += wq * f0.y;
                acc.z += wq * f1.x;
                acc.w += wq * f1.y;
            }
        }
    }
    float dsum = dpart;
    dsum += __shfl_xor_sync(0xffffffffu, dsum, 8);
    dsum += __shfl_xor_sync(0xffffffffu, dsum, 16);
    float dh = __shfl_sync(0xffffffffu, dsum, h);
    float inv = 1.f / (dh + 1e-16f);
    float4 bb = *(const float4*)&b1[lid * 4];
    float4 o;
    o.x = elu1(acc.x * inv + bb.x);
    o.y = elu1(acc.y * inv + bb.y);
    o.z = elu1(acc.z * inv + bb.z);
    o.w = elu1(acc.w * inv + bb.w);
    *(float4*)&g_x2[(size_t)warp * 128 + lid * 4] = o;
}

// ---------------- GEMM2 + att2 fold: h2h = fp16(x2@W2); as2/ad2 --------------
__global__ void gemm2_kernel(const float* __restrict__ B,
                             const float* __restrict__ att_s, const float* __restrict__ att_d,
                             int M) {
    const int K = 128, NC = 64;
    __shared__ float As[32][65];
    __shared__ float Bs[32][64];
    int tid = threadIdx.x;
    int blockRow = blockIdx.x * 64;
    int aRow = tid >> 3;
    int aCol = (tid & 7) << 2;
    int bRow = tid >> 4;
    int bCol = (tid & 15) << 2;
    int tRow = (tid >> 4) << 2;
    int tCol = (tid & 15) << 2;
    const float* A = g_x2;
    unsigned long long acc[4][2];
    #pragma unroll
    for (int i = 0; i < 4; i++) { acc[i][0] = 0ull; acc[i][1] = 0ull; }

    for (int k0 = 0; k0 < K; k0 += 32) {
        #pragma unroll
        for (int r = 0; r < 2; r++) {
            int row = blockRow + aRow + r * 32;
            float4 v = (row < M) ? *(const float4*)(A + (size_t)row * K + k0 + aCol)
                                 : make_float4(0.f, 0.f, 0.f, 0.f);
            As[aCol + 0][aRow + r * 32] = v.x;
            As[aCol + 1][aRow + r * 32] = v.y;
            As[aCol + 2][aRow + r * 32] = v.z;
            As[aCol + 3][aRow + r * 32] = v.w;
        }
        #pragma unroll
        for (int r = 0; r < 2; r++) {
            int row = bRow + r * 16;
            *(float4*)&Bs[row][bCol] = *(const float4*)(B + (size_t)(k0 + row) * NC + bCol);
        }
        __syncthreads();
        #pragma unroll
        for (int k = 0; k < 32; k++) {
            unsigned long long ap[4];
            ap[0] = pack2b(As[k][tRow]);
            ap[1] = pack2b(As[k][tRow + 1]);
            ap[2] = pack2b(As[k][tRow + 2]);
            ap[3] = pack2b(As[k][tRow + 3]);
            float4 bv = *(float4*)&Bs[k][tCol];
            unsigned long long bp0 = pack2f(bv.x, bv.y);
            unsigned long long bp1 = pack2f(bv.z, bv.w);
            #pragma unroll
            for (int i = 0; i < 4; i++) { ffma2(acc[i][0], ap[i], bp0); ffma2(acc[i][1], ap[i], bp1); }
        }
        __syncthreads();
    }

    float as_v[4], ad_v[4];
    #pragma unroll
    for (int j = 0; j < 4; j++) {
        as_v[j] = __ldg(&att_s[tCol + j]);
        ad_v[j] = __ldg(&att_d[tCol + j]);
    }
    #pragma unroll
    for (int i = 0; i < 4; i++) {
        int row = blockRow + tRow + i;
        float o[4];
        unpack2(acc[i][0], o[0], o[1]);
        unpack2(acc[i][1], o[2], o[3]);
        __half hb[4];
        #pragma unroll
        for (int j = 0; j < 4; j++) hb[j] = __float2half_rn(o[j]);
        float s = 0.f, d = 0.f;
        #pragma unroll
        for (int j = 0; j < 4; j++) { s += o[j] * as_v[j]; d += o[j] * ad_v[j]; }
        #pragma unroll
        for (int off = 1; off < 16; off <<= 1) {
            s += __shfl_xor_sync(0xffffffffu, s, off);
            d += __shfl_xor_sync(0xffffffffu, d, off);
        }
        if (row < M) {
            *(uint2*)&g_h2h[(size_t)row * 64 + tCol] = *(uint2*)hb;
            if ((tid & 15) == 0) {
                g_as2[row] = s;
                g_ad2[row] = d;
            }
        }
    }
}

// ---------------- layer-2 gather (fp16) + bias + log_softmax -----------------
__global__ void gat2_kernel(const float* __restrict__ b2, float* __restrict__ out, int n) {
    int warp = (blockIdx.x * blockDim.x + threadIdx.x) >> 5;
    int lid = threadIdx.x & 31;
    if (warp >= n) return;
    int beg = g_rowptr[warp], end = g_rowptr[warp + 1];
    float adn = g_ad2[warp];

    float acc0 = 0.f, acc1 = 0.f, dpart = 0.f;
    for (int base = beg; base < end; base += 32) {
        int cnt = end - base; if (cnt > 32) cnt = 32;
        int sidx = (base + lid < end) ? __ldg(&g_srcs[base + lid]) : 0;
        for (int g = 0; g < cnt; g += 4) {
            int widx = g + (lid & 3); if (widx > 31) widx = 31;
            int sj = __shfl_sync(0xffffffffu, sidx, widx);
            float w = 0.f;
            if (lid < 4 && g + lid < cnt)
                w = __expf(lrelu(__ldg(&g_as2[sj]) + adn));
            dpart += w;
            #pragma unroll
            for (int q = 0; q < 4; q++) {
                float wq = __shfl_sync(0xffffffffu, w, q);
                int   sq = __shfl_sync(0xffffffffu, sidx, g + q);
                __half2 hv = *(const __half2*)&g_h2h[(size_t)sq * 64 + lid * 2];
                float2 v = __half22float2(hv);
                acc0 += wq * v.x;
                acc1 += wq * v.y;
            }
        }
    }
    float dsum = dpart;
    dsum += __shfl_xor_sync(0xffffffffu, dsum, 1);
    dsum += __shfl_xor_sync(0xffffffffu, dsum, 2);
    float dt = __shfl_sync(0xffffffffu, dsum, 0);
    float inv = 1.f / (dt + 1e-16f);
    float o0 = acc0 * inv + __ldg(&b2[lid * 2]);
    float o1 = acc1 * inv + __ldg(&b2[lid * 2 + 1]);

    float rm = fmaxf(o0, o1);
    #pragma unroll
    for (int off = 16; off; off >>= 1)
        rm = fmaxf(rm, __shfl_xor_sync(0xffffffffu, rm, off));
    float se = __expf(o0 - rm) + __expf(o1 - rm);
    #pragma unroll
    for (int off = 16; off; off >>= 1)
        se += __shfl_xor_sync(0xffffffffu, se, off);
    float lse = rm + __logf(se);

    float2 res;
    res.x = o0 - lse;
    res.y = o1 - lse;
    *(float2*)&out[(size_t)warp * 64 + lid * 2] = res;
}

// ---------------- launch ------------------------------------------------------
extern "C" void kernel_launch(void* const* d_in, const int* in_sizes, int n_in,
                              void* d_out, int out_size) {
    const float* x      = (const float*)d_in[0];
    const int*   ei     = (const int*)d_in[1];
    const float* W1     = (const float*)d_in[2];
    const float* att1_s = (const float*)d_in[3];
    const float* att1_d = (const float*)d_in[4];
    const float* b1     = (const float*)d_in[5];
    const float* W2     = (const float*)d_in[6];
    const float* att2_s = (const float*)d_in[7];
    const float* att2_d = (const float*)d_in[8];
    const float* b2     = (const float*)d_in[9];
    float* out = (float*)d_out;

    int n = in_sizes[0] / 256;
    int e = in_sizes[1] / 2;
    int nb = (n + 1023) / 1024;

    static cudaStream_t s2 = nullptr;
    static cudaEvent_t evFork = nullptr, evJoin = nullptr;
    if (!s2) {
        cudaStreamCreateWithFlags(&s2, cudaStreamNonBlocking);
        cudaEventCreateWithFlags(&evFork, cudaEventDisableTiming);
        cudaEventCreateWithFlags(&evJoin, cudaEventDisableTiming);
    }

    // fork: gemm1 (+folded att1) runs concurrently with the CSR build
    cudaEventRecord(evFork, 0);
    cudaStreamWaitEvent(s2, evFork, 0);
    gemm1_kernel<<<(n + 63) / 64, 256, 0, s2>>>(x, W1, att1_s, att1_d, n);
    cudaEventRecord(evJoin, s2);

    // CSR build (by dst) on the main stream
    zero_cnt_kernel<<<(n + 255) / 256, 256>>>(n);
    hist_kernel<<<(e + 255) / 256, 256>>>(ei, e);
    scan1_kernel<<<nb, 1024>>>(n);
    scan2_kernel<<<1, 512>>>(nb);
    scan3_kernel<<<nb, 1024>>>(n);
    scatter_kernel<<<(e + 255) / 256, 256>>>(ei, e);

    // join, then the dependent chain
    cudaStreamWaitEvent(0, evJoin, 0);
    gat1_kernel<<<(n + 7) / 8, 256>>>(b1, n);
    gemm2_kernel<<<(n + 63) / 64, 256>>>(W2, att2_s, att2_d, n);
    gat2_kernel<<<(n + 7) / 8, 256>>>(b2, out, n);
}